// round 4
// baseline (speedup 1.0000x reference)
#include <cuda_runtime.h>
#include <math.h>

// ---------------------------------------------------------------------------
// Problem dims (fixed)
// ---------------------------------------------------------------------------
#define S_  2048
#define B_  2
#define E_  1024
#define H_  16
#define D_  64
#define M_  (S_ * B_)          // 4096 rows for the projection GEMMs
#define BHn (B_ * H_)          // 32 (b,h) batches

// ---------------------------------------------------------------------------
// Device scratch (static, allocation-guard-safe). 64 MB total.
// ---------------------------------------------------------------------------
__device__ float g_Q[(size_t)BHn * S_ * D_];    // [b][h][s][d]  16 MB
__device__ float g_K[(size_t)BHn * S_ * D_];    // [b][h][t][d]  16 MB
__device__ float g_V[(size_t)BHn * S_ * D_];    // [b][h][t][d]  16 MB
__device__ float g_ctx[(size_t)M_ * E_];        // [s][b][e]     16 MB

// ---------------------------------------------------------------------------
// Kernel 1: projection GEMM  C = A @ W^T + bias
//   A: (4096 x 1024) row-major, W: (1024 x 1024) row-major (nn.Linear weight)
//   mode 0/1/2 -> scatter into g_Q/g_K/g_V as [b][h][s|t][d]
//   mode 3     -> A is g_ctx, write plain row-major into outp (final output)
// Tiling: 64x64 block tile, BK=32, 256 threads, 4x4 per-thread micro-tile.
// ---------------------------------------------------------------------------
__global__ void __launch_bounds__(256)
qkvo_gemm(const float* __restrict__ A, const float* __restrict__ W,
          const float* __restrict__ bias, float* __restrict__ outp, int mode)
{
    __shared__ float As[32][68];   // [k][m], padded row (68*4 B)
    __shared__ float Bs[32][68];   // [k][n]

    const float* Ap = (mode == 3) ? g_ctx : A;

    const int tid = threadIdx.x;
    const int tx  = tid & 15;      // n
    const int ty  = tid >> 4;      // m
    const int bm  = blockIdx.y << 6;
    const int bn  = blockIdx.x << 6;

    float acc[4][4] = {};

    for (int k0 = 0; k0 < 1024; k0 += 32) {
        #pragma unroll
        for (int i = 0; i < 2; ++i) {
            int idx = tid + (i << 8);        // 0..511
            int r   = idx >> 3;              // 0..63 tile row
            int c   = (idx & 7) << 2;        // 0,4,...,28
            float4 va = *reinterpret_cast<const float4*>(
                Ap + (size_t)(bm + r) * 1024 + k0 + c);
            As[c + 0][r] = va.x; As[c + 1][r] = va.y;
            As[c + 2][r] = va.z; As[c + 3][r] = va.w;
            float4 vb = *reinterpret_cast<const float4*>(
                W + (size_t)(bn + r) * 1024 + k0 + c);
            Bs[c + 0][r] = vb.x; Bs[c + 1][r] = vb.y;
            Bs[c + 2][r] = vb.z; Bs[c + 3][r] = vb.w;
        }
        __syncthreads();

        #pragma unroll
        for (int kk = 0; kk < 32; ++kk) {
            float4 a4 = *reinterpret_cast<const float4*>(&As[kk][ty << 2]);
            float4 b4 = *reinterpret_cast<const float4*>(&Bs[kk][tx << 2]);
            float a[4] = {a4.x, a4.y, a4.z, a4.w};
            float b[4] = {b4.x, b4.y, b4.z, b4.w};
            #pragma unroll
            for (int i2 = 0; i2 < 4; ++i2)
                #pragma unroll
                for (int j2 = 0; j2 < 4; ++j2)
                    acc[i2][j2] += a[i2] * b[j2];
        }
        __syncthreads();
    }

    float* dst = (mode == 0) ? g_Q : (mode == 1) ? g_K : g_V;

    #pragma unroll
    for (int i2 = 0; i2 < 4; ++i2) {
        int m = bm + (ty << 2) + i2;
        #pragma unroll
        for (int j2 = 0; j2 < 4; ++j2) {
            int n = bn + (tx << 2) + j2;
            float v = acc[i2][j2] + bias[n];
            if (mode <= 2) {
                // row m of x -> (s = m/B, b = m%B); n = h*64 + d
                int s = m >> 1, b = m & 1;
                int h = n >> 6, d = n & 63;
                dst[((((size_t)b * H_ + h) * S_ + s) << 6) + d] = v;
            } else {
                outp[(size_t)m * 1024 + n] = v;
            }
        }
    }
}

// ---------------------------------------------------------------------------
// Kernel 2: FUSED attention (scores -> softmax over HEADS -> attn @ V).
//
// The reference softmax is over h at fixed (b,s,t), so it is local to a
// score tile: no cross-t running state. Each block owns 16 s-rows of one
// batch and streams over t-tiles of 16, keeping all 16 heads' 16x16 score
// blocks in smem. This removes the 512 MB scores tensor entirely.
//
// Smem (floats), bank-engineered:
//   sQ : [h][16 s][d], row stride 66, per-h stride 1058 (== 2 mod 32)
//   sKV: [h][16 t][d], same strides (holds K, then reused for V)
//   sSc: [h][16 s][17 t], per-h stride 273 (== 17 mod 32)
// Total 152,896 B dynamic smem (needs opt-in attribute; < 227 KB limit).
//
// Hazard ordering per t-iteration:
//   sync(A)  : prev AV reads of sKV/sSc complete -> K load may overwrite sKV
//   sync(B)  : K tile visible -> scores read sKV
//   sync(C)  : score writes to sSc visible -> softmax reads sSc;
//              scores also done READING sKV -> V load may overwrite sKV
//   sync(D)  : softmax writes + V tile visible -> AV reads sSc/sKV
// ---------------------------------------------------------------------------
#define RQ   66
#define PH   1058        // per-head plane stride for sQ / sKV
#define PS   273         // per-head plane stride for sSc
#define SM_F (16*PH /*Q*/ + 16*PH /*KV*/ + 16*PS /*Sc*/)
#define SM_BYTES (SM_F * 4)

__global__ void __launch_bounds__(256)
fused_attn()
{
    extern __shared__ float sm[];
    float* sQ  = sm;
    float* sKV = sm + 16 * PH;
    float* sSc = sm + 32 * PH;

    const int tid  = threadIdx.x;
    const int head = tid >> 4;
    const int sub  = tid & 15;
    // scores mapping: micro-tile 4s x 4t per thread
    const int ssA  = (sub & 3) << 2;     // s base
    const int ttA  = (sub >> 2) << 2;    // t base
    // AV mapping: micro-tile 4s x 16d (d in 4 chunks strided by 16)
    const int sdB  = (sub & 3) << 2;     // d base
    const int ssB  = (sub >> 2) << 2;    // s base

    const int s0 = blockIdx.x << 4;      // 16 s rows per block
    const int b  = blockIdx.y;

    // ---- load Q tile once: 16 h x 16 s x 64 d ------------------------------
    #pragma unroll
    for (int i = 0; i < 16; ++i) {
        int f   = tid + (i << 8);        // float4 index, 0..4095
        int h   = f >> 8;
        int rem = f & 255;
        int s   = rem >> 4;
        int dq  = (rem & 15) << 2;
        float4 v = *reinterpret_cast<const float4*>(
            g_Q + ((((size_t)b * H_ + h) * S_ + s0 + s) << 6) + dq);
        float* p = sQ + h * PH + s * RQ + dq;
        p[0] = v.x; p[1] = v.y; p[2] = v.z; p[3] = v.w;
    }

    float acc[4][16] = {};               // AV output accumulators

    for (int it = 0; it < S_ / 16; ++it) {
        const int t0 = it << 4;

        __syncthreads();                                     // sync(A)
        // ---- load K tile: 16 h x 16 t x 64 d -------------------------------
        #pragma unroll
        for (int i = 0; i < 16; ++i) {
            int f   = tid + (i << 8);
            int h   = f >> 8;
            int rem = f & 255;
            int t   = rem >> 4;
            int dq  = (rem & 15) << 2;
            float4 v = *reinterpret_cast<const float4*>(
                g_K + ((((size_t)b * H_ + h) * S_ + t0 + t) << 6) + dq);
            float* p = sKV + h * PH + t * RQ + dq;
            p[0] = v.x; p[1] = v.y; p[2] = v.z; p[3] = v.w;
        }
        __syncthreads();                                     // sync(B)

        // ---- scores: 4s x 4t micro-tile per thread, K-dim 64 ---------------
        {
            float sc[4][4] = {};
            const float* qb = sQ  + head * PH;
            const float* kb = sKV + head * PH;
            #pragma unroll
            for (int d2 = 0; d2 < 32; ++d2) {
                int d = d2 << 1;
                float2 qv[4], kv[4];
                #pragma unroll
                for (int i = 0; i < 4; ++i)
                    qv[i] = *reinterpret_cast<const float2*>(qb + (ssA + i) * RQ + d);
                #pragma unroll
                for (int j = 0; j < 4; ++j)
                    kv[j] = *reinterpret_cast<const float2*>(kb + (ttA + j) * RQ + d);
                #pragma unroll
                for (int i = 0; i < 4; ++i)
                    #pragma unroll
                    for (int j = 0; j < 4; ++j)
                        sc[i][j] += qv[i].x * kv[j].x + qv[i].y * kv[j].y;
            }
            float* scb = sSc + head * PS;
            #pragma unroll
            for (int i = 0; i < 4; ++i)
                #pragma unroll
                for (int j = 0; j < 4; ++j)
                    scb[(ssA + i) * 17 + (ttA + j)] = sc[i][j] * 0.125f;
        }
        __syncthreads();                                     // sync(C)

        // ---- softmax over heads (one (s,t) pair per thread) ----------------
        {
            int s = tid >> 4, t = tid & 15;
            float* base = sSc + s * 17 + t;
            float v[H_];
            float mx = -1e30f;
            #pragma unroll
            for (int h = 0; h < H_; ++h) {
                v[h] = base[h * PS];
                mx = fmaxf(mx, v[h]);
            }
            float sum = 0.f;
            #pragma unroll
            for (int h = 0; h < H_; ++h) {
                v[h] = __expf(v[h] - mx);
                sum += v[h];
            }
            float inv = 1.0f / sum;
            #pragma unroll
            for (int h = 0; h < H_; ++h)
                base[h * PS] = v[h] * inv;
        }

        // ---- load V tile into sKV (scores finished reading K at sync(C)) ---
        #pragma unroll
        for (int i = 0; i < 16; ++i) {
            int f   = tid + (i << 8);
            int h   = f >> 8;
            int rem = f & 255;
            int t   = rem >> 4;
            int dq  = (rem & 15) << 2;
            float4 v = *reinterpret_cast<const float4*>(
                g_V + ((((size_t)b * H_ + h) * S_ + t0 + t) << 6) + dq);
            float* p = sKV + h * PH + t * RQ + dq;
            p[0] = v.x; p[1] = v.y; p[2] = v.z; p[3] = v.w;
        }
        __syncthreads();                                     // sync(D)

        // ---- AV: acc[4s][16d] += attn[4s][16t] @ V[16t][16d] ---------------
        {
            const float* ab = sSc + head * PS;
            const float* vb = sKV + head * PH;
            #pragma unroll
            for (int k = 0; k < 16; ++k) {
                float a[4];
                #pragma unroll
                for (int i = 0; i < 4; ++i)
                    a[i] = ab[(ssB + i) * 17 + k];
                const float* vr = vb + k * RQ;
                #pragma unroll
                for (int c = 0; c < 4; ++c) {
                    float2 v0 = *reinterpret_cast<const float2*>(vr + sdB + (c << 4));
                    float2 v1 = *reinterpret_cast<const float2*>(vr + sdB + (c << 4) + 2);
                    #pragma unroll
                    for (int i = 0; i < 4; ++i) {
                        acc[i][(c << 2) + 0] += a[i] * v0.x;
                        acc[i][(c << 2) + 1] += a[i] * v0.y;
                        acc[i][(c << 2) + 2] += a[i] * v1.x;
                        acc[i][(c << 2) + 3] += a[i] * v1.y;
                    }
                }
            }
        }
    }

    // ---- write context tile: layout [s][b][h*64+d] -------------------------
    #pragma unroll
    for (int i = 0; i < 4; ++i) {
        int sg = s0 + ssB + i;
        float* ob = g_ctx + ((size_t)sg * B_ + b) * E_ + head * 64;
        #pragma unroll
        for (int c = 0; c < 4; ++c)
            #pragma unroll
            for (int e = 0; e < 4; ++e)
                ob[sdB + (c << 4) + e] = acc[i][(c << 2) + e];
    }
}

// ---------------------------------------------------------------------------
// Launch: graph-capturable (pure kernel launches; the attribute set is a
// host-side, non-stream call and also runs on the pre-capture correctness
// invocation). Inputs (metadata order): x, Wq, bq, Wk, bk, Wv, bv, Wo, bo
// ---------------------------------------------------------------------------
extern "C" void kernel_launch(void* const* d_in, const int* in_sizes, int n_in,
                              void* d_out, int out_size)
{
    const float* x  = (const float*)d_in[0];
    const float* Wq = (const float*)d_in[1];
    const float* bq = (const float*)d_in[2];
    const float* Wk = (const float*)d_in[3];
    const float* bk = (const float*)d_in[4];
    const float* Wv = (const float*)d_in[5];
    const float* bv = (const float*)d_in[6];
    const float* Wo = (const float*)d_in[7];
    const float* bo = (const float*)d_in[8];
    float* out = (float*)d_out;

    cudaFuncSetAttribute(fused_attn,
                         cudaFuncAttributeMaxDynamicSharedMemorySize, SM_BYTES);

    dim3 blk(256);
    dim3 gProj(E_ / 64, M_ / 64);            // 16 x 64

    qkvo_gemm<<<gProj, blk>>>(x, Wq, bq, nullptr, 0);
    qkvo_gemm<<<gProj, blk>>>(x, Wk, bk, nullptr, 1);
    qkvo_gemm<<<gProj, blk>>>(x, Wv, bv, nullptr, 2);

    fused_attn<<<dim3(S_ / 16, B_), blk, SM_BYTES>>>();   // 128 x 2 blocks

    qkvo_gemm<<<gProj, blk>>>(nullptr, Wo, bo, out, 3);
}

// round 8
// speedup vs baseline: 1.2286x; 1.2286x over previous
#include <cuda_runtime.h>
#include <cuda_bf16.h>
#include <mma.h>
#include <math.h>

// ---------------------------------------------------------------------------
// Problem dims (fixed)
// ---------------------------------------------------------------------------
#define S_  2048
#define B_  2
#define E_  1024
#define H_  16
#define D_  64
#define M_  (S_ * B_)
#define BHn (B_ * H_)

// ---------------------------------------------------------------------------
// Device scratch (static, allocation-guard-safe). ~112 MB total.
// ---------------------------------------------------------------------------
__device__ float g_Q[(size_t)BHn * S_ * D_];
__device__ float g_K[(size_t)BHn * S_ * D_];
__device__ float g_V[(size_t)BHn * S_ * D_];
__device__ float g_ctx[(size_t)M_ * E_];

__device__ __align__(128) __nv_bfloat16 g_xh[(size_t)M_ * E_];
__device__ __align__(128) __nv_bfloat16 g_xl[(size_t)M_ * E_];
__device__ __align__(128) __nv_bfloat16 g_Wh[(size_t)4 * E_ * E_];
__device__ __align__(128) __nv_bfloat16 g_Wl[(size_t)4 * E_ * E_];
__device__ __align__(128) __nv_bfloat16 g_ch[(size_t)M_ * E_];
__device__ __align__(128) __nv_bfloat16 g_cl[(size_t)M_ * E_];

// ---------------------------------------------------------------------------
// Split fp32 -> bf16 hi + bf16 lo (residual). Vectorized by 4.
// ---------------------------------------------------------------------------
__global__ void __launch_bounds__(256)
conv_split(const float* __restrict__ src, __nv_bfloat16* __restrict__ hi,
           __nv_bfloat16* __restrict__ lo, int n4)
{
    int idx = blockIdx.x * 256 + threadIdx.x;
    if (idx >= n4) return;
    float4 vin = reinterpret_cast<const float4*>(src)[idx];
    float vals[4];
    vals[0] = vin.x; vals[1] = vin.y; vals[2] = vin.z; vals[3] = vin.w;
    __nv_bfloat16 hiv[4];
    __nv_bfloat16 lov[4];
    #pragma unroll
    for (int j = 0; j < 4; ++j) {
        hiv[j] = __float2bfloat16_rn(vals[j]);
        lov[j] = __float2bfloat16_rn(vals[j] - __bfloat162float(hiv[j]));
    }
    __nv_bfloat162* hp = reinterpret_cast<__nv_bfloat162*>(hi);
    __nv_bfloat162* lp = reinterpret_cast<__nv_bfloat162*>(lo);
    hp[2 * idx + 0] = __nv_bfloat162(hiv[0], hiv[1]);
    hp[2 * idx + 1] = __nv_bfloat162(hiv[2], hiv[3]);
    lp[2 * idx + 0] = __nv_bfloat162(lov[0], lov[1]);
    lp[2 * idx + 1] = __nv_bfloat162(lov[2], lov[3]);
}

// ---------------------------------------------------------------------------
// WMMA projection GEMM (NO inline asm): C[m][n] = sum_k A[m][k]*W[n][k] + b[n]
// bf16 (hi,lo) operands, fp32 accum, 3-product split: Ah*Wh + Ah*Wl + Al*Wh.
// M=4096 N=1024 K=1024. BM=BN=128, BK=16. 256 threads = 8 warps (2m x 4n),
// warp tile 64x32 = 4x2 wmma m16n16k16 fragments.
// Smem: 4 tiles (Ah,Al,Wh,Wl) of 128x16 bf16, rows padded to 24 bf16 (48 B:
// 48*r mod 128 spans all 8 16B-granules -> ldmatrix conflict-free),
// double-buffered; global->register prefetch overlaps compute.
// mode 0/1/2: scatter fp32 into g_Q/g_K/g_V [b][h][s][d]; mode 3: outp[m][n].
// ---------------------------------------------------------------------------
#define SKP        24
#define TILE_ELEMS (128 * SKP)
#define STAGE_ELEMS (4 * TILE_ELEMS)
#define GEMM_SMEM  (2 * STAGE_ELEMS * 2)     // bytes: 2 stages of bf16

using namespace nvcuda;

__global__ void __launch_bounds__(256)
wmma_gemm(const __nv_bfloat16* __restrict__ Ahp, const __nv_bfloat16* __restrict__ Alp,
          const __nv_bfloat16* __restrict__ Whp, const __nv_bfloat16* __restrict__ Wlp,
          const float* __restrict__ bias, float* __restrict__ outp, int mode)
{
    extern __shared__ __align__(16) unsigned char smraw[];
    __nv_bfloat16* smb = reinterpret_cast<__nv_bfloat16*>(smraw);

    const int tid    = threadIdx.x;
    const int lane   = tid & 31;
    const int warpid = tid >> 5;
    const int warpM  = (warpid >> 2) << 6;     // 0 / 64
    const int warpN  = (warpid & 3) << 5;      // 0,32,64,96
    const int blockM = blockIdx.y << 7;
    const int blockN = blockIdx.x << 7;

    const __nv_bfloat16* gA[4];
    gA[0] = Ahp + (size_t)blockM * 1024;
    gA[1] = Alp + (size_t)blockM * 1024;
    gA[2] = Whp + (size_t)blockN * 1024;
    gA[3] = Wlp + (size_t)blockN * 1024;

    // per-thread copy slot: one 16B chunk per tile per stage
    const int srow = tid >> 1;                 // 0..127
    const int shalf = tid & 1;                 // 0..1
    const size_t gbase = (size_t)srow * 1024 + (size_t)shalf * 8;
    const int soff = srow * SKP + shalf * 8;   // bf16 units

    wmma::fragment<wmma::accumulator, 16, 16, 16, float> accf[4][2];
    #pragma unroll
    for (int mi = 0; mi < 4; ++mi)
        #pragma unroll
        for (int nj = 0; nj < 2; ++nj)
            wmma::fill_fragment(accf[mi][nj], 0.0f);

    float4 pre[4];
    #pragma unroll
    for (int t = 0; t < 4; ++t)
        pre[t] = *reinterpret_cast<const float4*>(gA[t] + gbase);
    #pragma unroll
    for (int t = 0; t < 4; ++t)
        *reinterpret_cast<float4*>(smb + t * TILE_ELEMS + soff) = pre[t];

    for (int step = 0; step < 64; ++step) {
        if (step < 63) {
            size_t gk = gbase + (size_t)(step + 1) * 16;
            #pragma unroll
            for (int t = 0; t < 4; ++t)
                pre[t] = *reinterpret_cast<const float4*>(gA[t] + gk);
        }
        __syncthreads();

        const __nv_bfloat16* stg = smb + (step & 1) * STAGE_ELEMS;
        {
            wmma::fragment<wmma::matrix_a, 16, 16, 16, __nv_bfloat16, wmma::row_major> fAh[4];
            wmma::fragment<wmma::matrix_a, 16, 16, 16, __nv_bfloat16, wmma::row_major> fAl[4];
            wmma::fragment<wmma::matrix_b, 16, 16, 16, __nv_bfloat16, wmma::col_major> fBh[2];
            wmma::fragment<wmma::matrix_b, 16, 16, 16, __nv_bfloat16, wmma::col_major> fBl[2];
            #pragma unroll
            for (int mi = 0; mi < 4; ++mi) {
                wmma::load_matrix_sync(fAh[mi],
                    stg + 0 * TILE_ELEMS + (warpM + mi * 16) * SKP, SKP);
                wmma::load_matrix_sync(fAl[mi],
                    stg + 1 * TILE_ELEMS + (warpM + mi * 16) * SKP, SKP);
            }
            #pragma unroll
            for (int nj = 0; nj < 2; ++nj) {
                wmma::load_matrix_sync(fBh[nj],
                    stg + 2 * TILE_ELEMS + (warpN + nj * 16) * SKP, SKP);
                wmma::load_matrix_sync(fBl[nj],
                    stg + 3 * TILE_ELEMS + (warpN + nj * 16) * SKP, SKP);
            }
            #pragma unroll
            for (int mi = 0; mi < 4; ++mi) {
                #pragma unroll
                for (int nj = 0; nj < 2; ++nj) {
                    wmma::mma_sync(accf[mi][nj], fAh[mi], fBh[nj], accf[mi][nj]);
                    wmma::mma_sync(accf[mi][nj], fAh[mi], fBl[nj], accf[mi][nj]);
                    wmma::mma_sync(accf[mi][nj], fAl[mi], fBh[nj], accf[mi][nj]);
                }
            }
        }
        if (step < 63) {
            __nv_bfloat16* nstg = smb + ((step + 1) & 1) * STAGE_ELEMS;
            #pragma unroll
            for (int t = 0; t < 4; ++t)
                *reinterpret_cast<float4*>(nstg + t * TILE_ELEMS + soff) = pre[t];
        }
    }

    // ---- epilogue: stage frags through smem, add bias, scatter -------------
    __syncthreads();
    float* stgf = reinterpret_cast<float*>(smraw) + warpid * 576;   // 16x36

    float* dstQKV = (mode == 0) ? g_Q : (mode == 1) ? g_K : g_V;
    const int erow = lane >> 1;                 // 0..15
    const int ecol = (lane & 1) * 16;           // 0 / 16

    #pragma unroll
    for (int mi = 0; mi < 4; ++mi) {
        wmma::store_matrix_sync(stgf + 0,  accf[mi][0], 36, wmma::mem_row_major);
        wmma::store_matrix_sync(stgf + 16, accf[mi][1], 36, wmma::mem_row_major);
        __syncwarp();

        int mRow = blockM + warpM + mi * 16 + erow;
        int col0 = blockN + warpN + ecol;

        float vv[16];
        #pragma unroll
        for (int c = 0; c < 4; ++c) {
            float4 t4 = *reinterpret_cast<const float4*>(stgf + erow * 36 + ecol + c * 4);
            float4 b4 = *reinterpret_cast<const float4*>(bias + col0 + c * 4);
            vv[c * 4 + 0] = t4.x + b4.x;
            vv[c * 4 + 1] = t4.y + b4.y;
            vv[c * 4 + 2] = t4.z + b4.z;
            vv[c * 4 + 3] = t4.w + b4.w;
        }

        if (mode <= 2) {
            int sE = mRow >> 1;
            int bE = mRow & 1;
            int hE = col0 >> 6;
            int dE = col0 & 63;
            float* pd = dstQKV + ((((size_t)bE * H_ + hE) * S_ + sE) << 6) + dE;
            #pragma unroll
            for (int c = 0; c < 4; ++c)
                *reinterpret_cast<float4*>(pd + c * 4)
                    = make_float4(vv[c*4+0], vv[c*4+1], vv[c*4+2], vv[c*4+3]);
        } else {
            float* pd = outp + (size_t)mRow * 1024 + col0;
            #pragma unroll
            for (int c = 0; c < 4; ++c)
                *reinterpret_cast<float4*>(pd + c * 4)
                    = make_float4(vv[c*4+0], vv[c*4+1], vv[c*4+2], vv[c*4+3]);
        }
        __syncwarp();
    }
}

// ---------------------------------------------------------------------------
// FUSED attention (scores -> softmax over HEADS -> attn @ V). UNCHANGED from
// the round-4 passing kernel (proven correct); fp32 SIMT, no inline asm.
// ---------------------------------------------------------------------------
#define RQ   66
#define PH   1058
#define PS   273
#define SM_F (16*PH + 16*PH + 16*PS)
#define SM_BYTES (SM_F * 4)

__global__ void __launch_bounds__(256)
fused_attn()
{
    extern __shared__ float sm[];
    float* sQ  = sm;
    float* sKV = sm + 16 * PH;
    float* sSc = sm + 32 * PH;

    const int tid  = threadIdx.x;
    const int head = tid >> 4;
    const int sub  = tid & 15;
    const int ssA  = (sub & 3) << 2;
    const int ttA  = (sub >> 2) << 2;
    const int sdB  = (sub & 3) << 2;
    const int ssB  = (sub >> 2) << 2;

    const int s0 = blockIdx.x << 4;
    const int b  = blockIdx.y;

    #pragma unroll
    for (int i = 0; i < 16; ++i) {
        int f   = tid + (i << 8);
        int h   = f >> 8;
        int rem = f & 255;
        int s   = rem >> 4;
        int dq  = (rem & 15) << 2;
        float4 v = *reinterpret_cast<const float4*>(
            g_Q + ((((size_t)b * H_ + h) * S_ + s0 + s) << 6) + dq);
        float* p = sQ + h * PH + s * RQ + dq;
        p[0] = v.x; p[1] = v.y; p[2] = v.z; p[3] = v.w;
    }

    float acc[4][16] = {};

    for (int it = 0; it < S_ / 16; ++it) {
        const int t0 = it << 4;

        __syncthreads();
        #pragma unroll
        for (int i = 0; i < 16; ++i) {
            int f   = tid + (i << 8);
            int h   = f >> 8;
            int rem = f & 255;
            int t   = rem >> 4;
            int dq  = (rem & 15) << 2;
            float4 v = *reinterpret_cast<const float4*>(
                g_K + ((((size_t)b * H_ + h) * S_ + t0 + t) << 6) + dq);
            float* p = sKV + h * PH + t * RQ + dq;
            p[0] = v.x; p[1] = v.y; p[2] = v.z; p[3] = v.w;
        }
        __syncthreads();

        {
            float sc[4][4] = {};
            const float* qb = sQ  + head * PH;
            const float* kb = sKV + head * PH;
            #pragma unroll
            for (int d2 = 0; d2 < 32; ++d2) {
                int d = d2 << 1;
                float2 qv[4];
                float2 kv[4];
                #pragma unroll
                for (int i = 0; i < 4; ++i)
                    qv[i] = *reinterpret_cast<const float2*>(qb + (ssA + i) * RQ + d);
                #pragma unroll
                for (int j = 0; j < 4; ++j)
                    kv[j] = *reinterpret_cast<const float2*>(kb + (ttA + j) * RQ + d);
                #pragma unroll
                for (int i = 0; i < 4; ++i)
                    #pragma unroll
                    for (int j = 0; j < 4; ++j)
                        sc[i][j] += qv[i].x * kv[j].x + qv[i].y * kv[j].y;
            }
            float* scb = sSc + head * PS;
            #pragma unroll
            for (int i = 0; i < 4; ++i)
                #pragma unroll
                for (int j = 0; j < 4; ++j)
                    scb[(ssA + i) * 17 + (ttA + j)] = sc[i][j] * 0.125f;
        }
        __syncthreads();

        {
            int s = tid >> 4;
            int t = tid & 15;
            float* base = sSc + s * 17 + t;
            float v[H_];
            float mx = -1e30f;
            #pragma unroll
            for (int h = 0; h < H_; ++h) {
                v[h] = base[h * PS];
                mx = fmaxf(mx, v[h]);
            }
            float sum = 0.f;
            #pragma unroll
            for (int h = 0; h < H_; ++h) {
                v[h] = __expf(v[h] - mx);
                sum += v[h];
            }
            float inv = 1.0f / sum;
            #pragma unroll
            for (int h = 0; h < H_; ++h)
                base[h * PS] = v[h] * inv;
        }

        #pragma unroll
        for (int i = 0; i < 16; ++i) {
            int f   = tid + (i << 8);
            int h   = f >> 8;
            int rem = f & 255;
            int t   = rem >> 4;
            int dq  = (rem & 15) << 2;
            float4 v = *reinterpret_cast<const float4*>(
                g_V + ((((size_t)b * H_ + h) * S_ + t0 + t) << 6) + dq);
            float* p = sKV + h * PH + t * RQ + dq;
            p[0] = v.x; p[1] = v.y; p[2] = v.z; p[3] = v.w;
        }
        __syncthreads();

        {
            const float* ab = sSc + head * PS;
            const float* vb = sKV + head * PH;
            #pragma unroll
            for (int k = 0; k < 16; ++k) {
                float a[4];
                #pragma unroll
                for (int i = 0; i < 4; ++i)
                    a[i] = ab[(ssB + i) * 17 + k];
                const float* vr = vb + k * RQ;
                #pragma unroll
                for (int c = 0; c < 4; ++c) {
                    float2 v0 = *reinterpret_cast<const float2*>(vr + sdB + (c << 4));
                    float2 v1 = *reinterpret_cast<const float2*>(vr + sdB + (c << 4) + 2);
                    #pragma unroll
                    for (int i = 0; i < 4; ++i) {
                        acc[i][(c << 2) + 0] += a[i] * v0.x;
                        acc[i][(c << 2) + 1] += a[i] * v0.y;
                        acc[i][(c << 2) + 2] += a[i] * v1.x;
                        acc[i][(c << 2) + 3] += a[i] * v1.y;
                    }
                }
            }
        }
    }

    #pragma unroll
    for (int i = 0; i < 4; ++i) {
        int sg = s0 + ssB + i;
        float* ob = g_ctx + ((size_t)sg * B_ + b) * E_ + head * 64;
        #pragma unroll
        for (int c = 0; c < 4; ++c)
            #pragma unroll
            for (int e = 0; e < 4; ++e)
                ob[sdB + (c << 4) + e] = acc[i][(c << 2) + e];
    }
}

// ---------------------------------------------------------------------------
// Launch. Inputs (metadata order): x, Wq, bq, Wk, bk, Wv, bv, Wo, bo
// ---------------------------------------------------------------------------
extern "C" void kernel_launch(void* const* d_in, const int* in_sizes, int n_in,
                              void* d_out, int out_size)
{
    const float* x  = (const float*)d_in[0];
    const float* Wq = (const float*)d_in[1];
    const float* bq = (const float*)d_in[2];
    const float* Wk = (const float*)d_in[3];
    const float* bk = (const float*)d_in[4];
    const float* Wv = (const float*)d_in[5];
    const float* bv = (const float*)d_in[6];
    const float* Wo = (const float*)d_in[7];
    const float* bo = (const float*)d_in[8];
    float* out = (float*)d_out;

    cudaFuncSetAttribute(fused_attn,
                         cudaFuncAttributeMaxDynamicSharedMemorySize, SM_BYTES);
    cudaFuncSetAttribute(wmma_gemm,
                         cudaFuncAttributeMaxDynamicSharedMemorySize, GEMM_SMEM);

    __nv_bfloat16* xh;
    __nv_bfloat16* xl;
    __nv_bfloat16* Wh;
    __nv_bfloat16* Wl;
    __nv_bfloat16* ch;
    __nv_bfloat16* cl;
    float* ctxp;
    cudaGetSymbolAddress((void**)&xh, g_xh);
    cudaGetSymbolAddress((void**)&xl, g_xl);
    cudaGetSymbolAddress((void**)&Wh, g_Wh);
    cudaGetSymbolAddress((void**)&Wl, g_Wl);
    cudaGetSymbolAddress((void**)&ch, g_ch);
    cudaGetSymbolAddress((void**)&cl, g_cl);
    cudaGetSymbolAddress((void**)&ctxp, g_ctx);

    const size_t WSZ = (size_t)E_ * E_;
    dim3 blk(256);

    conv_split<<<(M_ * E_ / 4 + 255) / 256, blk>>>(x,  xh, xl, M_ * E_ / 4);
    conv_split<<<(WSZ / 4 + 255) / 256, blk>>>(Wq, Wh + 0 * WSZ, Wl + 0 * WSZ, WSZ / 4);
    conv_split<<<(WSZ / 4 + 255) / 256, blk>>>(Wk, Wh + 1 * WSZ, Wl + 1 * WSZ, WSZ / 4);
    conv_split<<<(WSZ / 4 + 255) / 256, blk>>>(Wv, Wh + 2 * WSZ, Wl + 2 * WSZ, WSZ / 4);
    conv_split<<<(WSZ / 4 + 255) / 256, blk>>>(Wo, Wh + 3 * WSZ, Wl + 3 * WSZ, WSZ / 4);

    dim3 gGemm(E_ / 128, M_ / 128);
    wmma_gemm<<<gGemm, blk, GEMM_SMEM>>>(xh, xl, Wh + 0 * WSZ, Wl + 0 * WSZ,
                                         bq, nullptr, 0);
    wmma_gemm<<<gGemm, blk, GEMM_SMEM>>>(xh, xl, Wh + 1 * WSZ, Wl + 1 * WSZ,
                                         bk, nullptr, 1);
    wmma_gemm<<<gGemm, blk, GEMM_SMEM>>>(xh, xl, Wh + 2 * WSZ, Wl + 2 * WSZ,
                                         bv, nullptr, 2);

    fused_attn<<<dim3(S_ / 16, B_), blk, SM_BYTES>>>();

    conv_split<<<(M_ * E_ / 4 + 255) / 256, blk>>>(ctxp, ch, cl, M_ * E_ / 4);
    wmma_gemm<<<gGemm, blk, GEMM_SMEM>>>(ch, cl, Wh + 3 * WSZ, Wl + 3 * WSZ,
                                         bo, out, 3);
}

// round 10
// speedup vs baseline: 2.3050x; 1.8761x over previous
#include <cuda_runtime.h>
#include <cuda_bf16.h>
#include <mma.h>
#include <math.h>

// ---------------------------------------------------------------------------
// Problem dims (fixed)
// ---------------------------------------------------------------------------
#define S_  2048
#define B_  2
#define E_  1024
#define H_  16
#define D_  64
#define M_  (S_ * B_)
#define BHn (B_ * H_)
#define ST_ ((size_t)S_ * S_)

// ---------------------------------------------------------------------------
// Device scratch (static). ~1.2 GB total.
// ---------------------------------------------------------------------------
__device__ __align__(128) __nv_bfloat16 g_Qh[(size_t)BHn * S_ * D_];
__device__ __align__(128) __nv_bfloat16 g_Ql[(size_t)BHn * S_ * D_];
__device__ __align__(128) __nv_bfloat16 g_Kh[(size_t)BHn * S_ * D_];
__device__ __align__(128) __nv_bfloat16 g_Kl[(size_t)BHn * S_ * D_];
__device__ __align__(128) __nv_bfloat16 g_Vh[(size_t)BHn * S_ * D_];
__device__ __align__(128) __nv_bfloat16 g_Vl[(size_t)BHn * S_ * D_];
__device__ float g_P[(size_t)BHn * ST_];                 // fp32 scores 512 MB
__device__ __align__(128) __nv_bfloat16 g_Ph[(size_t)BHn * ST_];
__device__ __align__(128) __nv_bfloat16 g_Pl[(size_t)BHn * ST_];
__device__ float g_ctx[(size_t)M_ * E_];

__device__ __align__(128) __nv_bfloat16 g_xh[(size_t)M_ * E_];
__device__ __align__(128) __nv_bfloat16 g_xl[(size_t)M_ * E_];
__device__ __align__(128) __nv_bfloat16 g_Wh[(size_t)4 * E_ * E_];
__device__ __align__(128) __nv_bfloat16 g_Wl[(size_t)4 * E_ * E_];
__device__ __align__(128) __nv_bfloat16 g_ch[(size_t)M_ * E_];
__device__ __align__(128) __nv_bfloat16 g_cl[(size_t)M_ * E_];

using namespace nvcuda;

// ---------------------------------------------------------------------------
// Split fp32 -> bf16 hi + bf16 lo (residual). Vectorized by 4.
// ---------------------------------------------------------------------------
__global__ void __launch_bounds__(256)
conv_split(const float* __restrict__ src, __nv_bfloat16* __restrict__ hi,
           __nv_bfloat16* __restrict__ lo, int n4)
{
    int idx = blockIdx.x * 256 + threadIdx.x;
    if (idx >= n4) return;
    float4 vin = reinterpret_cast<const float4*>(src)[idx];
    float vals[4];
    vals[0] = vin.x; vals[1] = vin.y; vals[2] = vin.z; vals[3] = vin.w;
    __nv_bfloat16 hiv[4];
    __nv_bfloat16 lov[4];
    #pragma unroll
    for (int j = 0; j < 4; ++j) {
        hiv[j] = __float2bfloat16_rn(vals[j]);
        lov[j] = __float2bfloat16_rn(vals[j] - __bfloat162float(hiv[j]));
    }
    __nv_bfloat162* hp = reinterpret_cast<__nv_bfloat162*>(hi);
    __nv_bfloat162* lp = reinterpret_cast<__nv_bfloat162*>(lo);
    hp[2 * idx + 0] = __nv_bfloat162(hiv[0], hiv[1]);
    hp[2 * idx + 1] = __nv_bfloat162(hiv[2], hiv[3]);
    lp[2 * idx + 0] = __nv_bfloat162(lov[0], lov[1]);
    lp[2 * idx + 1] = __nv_bfloat162(lov[2], lov[3]);
}

// ---------------------------------------------------------------------------
// WMMA projection GEMM. C[m][n] = sum_k A[m][k]*W[n][k] + b[n].
// bf16 hi/lo 3-product split. BM=BN=128, BK=32, 2-stage smem, reg prefetch.
// Rows padded to 40 bf16 (80 B): 80r mod 128 = {0,80,32,112,64,16,96,48}.
// mode 0/1/2: write bf16 hi/lo into g_Q*/g_K*/g_V* [b][h][s][d].
// mode 3: write fp32 outp[m][n].
// ---------------------------------------------------------------------------
#define SKP        40
#define TILE_E     (128 * SKP)
#define STAGE_E    (4 * TILE_E)
#define GEMM_SMEM  (2 * STAGE_E * 2)

__global__ void __launch_bounds__(256)
wmma_gemm(const __nv_bfloat16* __restrict__ Ahp, const __nv_bfloat16* __restrict__ Alp,
          const __nv_bfloat16* __restrict__ Whp, const __nv_bfloat16* __restrict__ Wlp,
          const float* __restrict__ bias, float* __restrict__ outp, int mode)
{
    extern __shared__ __align__(16) unsigned char smraw[];
    __nv_bfloat16* smb = reinterpret_cast<__nv_bfloat16*>(smraw);

    const int tid    = threadIdx.x;
    const int lane   = tid & 31;
    const int warpid = tid >> 5;
    const int warpM  = (warpid >> 2) << 6;
    const int warpN  = (warpid & 3) << 5;
    const int blockM = blockIdx.y << 7;
    const int blockN = blockIdx.x << 7;

    const __nv_bfloat16* gT[4];
    gT[0] = Ahp + (size_t)blockM * 1024;
    gT[1] = Alp + (size_t)blockM * 1024;
    gT[2] = Whp + (size_t)blockN * 1024;
    gT[3] = Wlp + (size_t)blockN * 1024;

    const int srow  = tid >> 1;
    const int shalf = tid & 1;

    wmma::fragment<wmma::accumulator, 16, 16, 16, float> accf[4][2];
    #pragma unroll
    for (int mi = 0; mi < 4; ++mi)
        #pragma unroll
        for (int nj = 0; nj < 2; ++nj)
            wmma::fill_fragment(accf[mi][nj], 0.0f);

    float4 pre[8];
    #pragma unroll
    for (int t = 0; t < 4; ++t)
        #pragma unroll
        for (int c = 0; c < 2; ++c)
            pre[t * 2 + c] = *reinterpret_cast<const float4*>(
                gT[t] + (size_t)srow * 1024 + (size_t)(shalf * 2 + c) * 8);
    #pragma unroll
    for (int t = 0; t < 4; ++t)
        #pragma unroll
        for (int c = 0; c < 2; ++c)
            *reinterpret_cast<float4*>(
                smb + t * TILE_E + srow * SKP + (shalf * 2 + c) * 8) = pre[t * 2 + c];

    for (int step = 0; step < 32; ++step) {
        if (step < 31) {
            size_t k0 = (size_t)(step + 1) * 32;
            #pragma unroll
            for (int t = 0; t < 4; ++t)
                #pragma unroll
                for (int c = 0; c < 2; ++c)
                    pre[t * 2 + c] = *reinterpret_cast<const float4*>(
                        gT[t] + (size_t)srow * 1024 + k0 + (size_t)(shalf * 2 + c) * 8);
        }
        __syncthreads();

        const __nv_bfloat16* stg = smb + (step & 1) * STAGE_E;
        #pragma unroll
        for (int kk = 0; kk < 2; ++kk) {
            wmma::fragment<wmma::matrix_a, 16, 16, 16, __nv_bfloat16, wmma::row_major> fAh[4];
            wmma::fragment<wmma::matrix_a, 16, 16, 16, __nv_bfloat16, wmma::row_major> fAl[4];
            wmma::fragment<wmma::matrix_b, 16, 16, 16, __nv_bfloat16, wmma::col_major> fBh[2];
            wmma::fragment<wmma::matrix_b, 16, 16, 16, __nv_bfloat16, wmma::col_major> fBl[2];
            #pragma unroll
            for (int mi = 0; mi < 4; ++mi) {
                wmma::load_matrix_sync(fAh[mi],
                    stg + 0 * TILE_E + (warpM + mi * 16) * SKP + kk * 16, SKP);
                wmma::load_matrix_sync(fAl[mi],
                    stg + 1 * TILE_E + (warpM + mi * 16) * SKP + kk * 16, SKP);
            }
            #pragma unroll
            for (int nj = 0; nj < 2; ++nj) {
                wmma::load_matrix_sync(fBh[nj],
                    stg + 2 * TILE_E + (warpN + nj * 16) * SKP + kk * 16, SKP);
                wmma::load_matrix_sync(fBl[nj],
                    stg + 3 * TILE_E + (warpN + nj * 16) * SKP + kk * 16, SKP);
            }
            #pragma unroll
            for (int mi = 0; mi < 4; ++mi) {
                #pragma unroll
                for (int nj = 0; nj < 2; ++nj) {
                    wmma::mma_sync(accf[mi][nj], fAh[mi], fBh[nj], accf[mi][nj]);
                    wmma::mma_sync(accf[mi][nj], fAh[mi], fBl[nj], accf[mi][nj]);
                    wmma::mma_sync(accf[mi][nj], fAl[mi], fBh[nj], accf[mi][nj]);
                }
            }
        }
        if (step < 31) {
            __nv_bfloat16* nstg = smb + ((step + 1) & 1) * STAGE_E;
            #pragma unroll
            for (int t = 0; t < 4; ++t)
                #pragma unroll
                for (int c = 0; c < 2; ++c)
                    *reinterpret_cast<float4*>(
                        nstg + t * TILE_E + srow * SKP + (shalf * 2 + c) * 8) = pre[t * 2 + c];
        }
    }

    // ---- epilogue ----------------------------------------------------------
    __syncthreads();
    float* stgf = reinterpret_cast<float*>(smraw) + warpid * 576;   // 16x36

    __nv_bfloat16* dsth = (mode == 0) ? g_Qh : (mode == 1) ? g_Kh : g_Vh;
    __nv_bfloat16* dstl = (mode == 0) ? g_Ql : (mode == 1) ? g_Kl : g_Vl;

    const int erow = lane >> 1;
    const int ecol = (lane & 1) * 16;

    #pragma unroll
    for (int mi = 0; mi < 4; ++mi) {
        wmma::store_matrix_sync(stgf + 0,  accf[mi][0], 36, wmma::mem_row_major);
        wmma::store_matrix_sync(stgf + 16, accf[mi][1], 36, wmma::mem_row_major);
        __syncwarp();

        int mRow = blockM + warpM + mi * 16 + erow;
        int col0 = blockN + warpN + ecol;

        float vv[16];
        #pragma unroll
        for (int c = 0; c < 4; ++c) {
            float4 t4 = *reinterpret_cast<const float4*>(stgf + erow * 36 + ecol + c * 4);
            float4 b4 = *reinterpret_cast<const float4*>(bias + col0 + c * 4);
            vv[c * 4 + 0] = t4.x + b4.x;
            vv[c * 4 + 1] = t4.y + b4.y;
            vv[c * 4 + 2] = t4.z + b4.z;
            vv[c * 4 + 3] = t4.w + b4.w;
        }

        if (mode <= 2) {
            int sE = mRow >> 1;
            int bE = mRow & 1;
            int hE = col0 >> 6;
            int dE = col0 & 63;
            unsigned int pwh[8];
            unsigned int pwl[8];
            #pragma unroll
            for (int j = 0; j < 8; ++j) {
                __nv_bfloat16 h0 = __float2bfloat16_rn(vv[2 * j]);
                __nv_bfloat16 h1 = __float2bfloat16_rn(vv[2 * j + 1]);
                __nv_bfloat16 l0 = __float2bfloat16_rn(vv[2 * j] - __bfloat162float(h0));
                __nv_bfloat16 l1 = __float2bfloat16_rn(vv[2 * j + 1] - __bfloat162float(h1));
                pwh[j] = (unsigned int)__bfloat16_as_ushort(h0)
                       | ((unsigned int)__bfloat16_as_ushort(h1) << 16);
                pwl[j] = (unsigned int)__bfloat16_as_ushort(l0)
                       | ((unsigned int)__bfloat16_as_ushort(l1) << 16);
            }
            size_t base = ((((size_t)bE * H_ + hE) * S_ + sE) << 6) + dE;
            uint4* ph = reinterpret_cast<uint4*>(dsth + base);
            uint4* pl = reinterpret_cast<uint4*>(dstl + base);
            ph[0] = make_uint4(pwh[0], pwh[1], pwh[2], pwh[3]);
            ph[1] = make_uint4(pwh[4], pwh[5], pwh[6], pwh[7]);
            pl[0] = make_uint4(pwl[0], pwl[1], pwl[2], pwl[3]);
            pl[1] = make_uint4(pwl[4], pwl[5], pwl[6], pwl[7]);
        } else {
            float* pd = outp + (size_t)mRow * 1024 + col0;
            #pragma unroll
            for (int c = 0; c < 4; ++c)
                *reinterpret_cast<float4*>(pd + c * 4)
                    = make_float4(vv[c*4+0], vv[c*4+1], vv[c*4+2], vv[c*4+3]);
        }
        __syncwarp();
    }
}

// ---------------------------------------------------------------------------
// Scores: P[bh][s][t] = (Q_bh . K_bh^T) / 8, bf16 hi/lo 3-product split.
// BM=BN=128, K=64 one-shot. Rows padded to 72 bf16 (144 B -> conflict-free).
// Loader: each of 256 threads copies 4 float4 per buffer (full 64 cols).
// ---------------------------------------------------------------------------
#define AKP        72
#define SC_TILE_E  (128 * AKP)
#define SC_SMEM    (4 * SC_TILE_E * 2)

__global__ void __launch_bounds__(256)
scores_wmma()
{
    extern __shared__ __align__(16) unsigned char smraw[];
    __nv_bfloat16* smb = reinterpret_cast<__nv_bfloat16*>(smraw);
    __nv_bfloat16* sQh = smb;
    __nv_bfloat16* sQl = smb + SC_TILE_E;
    __nv_bfloat16* sKh = smb + 2 * SC_TILE_E;
    __nv_bfloat16* sKl = smb + 3 * SC_TILE_E;

    const int tid    = threadIdx.x;
    const int warpid = tid >> 5;
    const int warpM  = (warpid >> 2) << 6;     // 0 / 64
    const int warpN  = (warpid & 3) << 5;      // 0..96
    const int blockM = blockIdx.y << 7;        // s tile
    const int blockN = blockIdx.x << 7;        // t tile
    const int bh     = blockIdx.z;

    const size_t qoff = (size_t)bh * (S_ * D_);
    const int srow  = tid >> 1;
    const int shalf = tid & 1;

    // full coverage: srow x (shalf*4 + c)*8, c in 0..3  -> 64 cols
    #pragma unroll
    for (int c = 0; c < 4; ++c) {
        int scol = shalf * 4 + c;              // 0..7
        size_t gq = qoff + (size_t)(blockM + srow) * 64 + scol * 8;
        size_t gk = qoff + (size_t)(blockN + srow) * 64 + scol * 8;
        int so = srow * AKP + scol * 8;
        *reinterpret_cast<float4*>(sQh + so) = *reinterpret_cast<const float4*>(g_Qh + gq);
        *reinterpret_cast<float4*>(sQl + so) = *reinterpret_cast<const float4*>(g_Ql + gq);
        *reinterpret_cast<float4*>(sKh + so) = *reinterpret_cast<const float4*>(g_Kh + gk);
        *reinterpret_cast<float4*>(sKl + so) = *reinterpret_cast<const float4*>(g_Kl + gk);
    }
    __syncthreads();

    wmma::fragment<wmma::accumulator, 16, 16, 16, float> accf[4][2];
    #pragma unroll
    for (int mi = 0; mi < 4; ++mi)
        #pragma unroll
        for (int nj = 0; nj < 2; ++nj)
            wmma::fill_fragment(accf[mi][nj], 0.0f);

    #pragma unroll
    for (int kk = 0; kk < 4; ++kk) {
        wmma::fragment<wmma::matrix_a, 16, 16, 16, __nv_bfloat16, wmma::row_major> fAh[4];
        wmma::fragment<wmma::matrix_a, 16, 16, 16, __nv_bfloat16, wmma::row_major> fAl[4];
        wmma::fragment<wmma::matrix_b, 16, 16, 16, __nv_bfloat16, wmma::col_major> fBh[2];
        wmma::fragment<wmma::matrix_b, 16, 16, 16, __nv_bfloat16, wmma::col_major> fBl[2];
        #pragma unroll
        for (int mi = 0; mi < 4; ++mi) {
            wmma::load_matrix_sync(fAh[mi], sQh + (warpM + mi * 16) * AKP + kk * 16, AKP);
            wmma::load_matrix_sync(fAl[mi], sQl + (warpM + mi * 16) * AKP + kk * 16, AKP);
        }
        #pragma unroll
        for (int nj = 0; nj < 2; ++nj) {
            wmma::load_matrix_sync(fBh[nj], sKh + (warpN + nj * 16) * AKP + kk * 16, AKP);
            wmma::load_matrix_sync(fBl[nj], sKl + (warpN + nj * 16) * AKP + kk * 16, AKP);
        }
        #pragma unroll
        for (int mi = 0; mi < 4; ++mi) {
            #pragma unroll
            for (int nj = 0; nj < 2; ++nj) {
                wmma::mma_sync(accf[mi][nj], fAh[mi], fBh[nj], accf[mi][nj]);
                wmma::mma_sync(accf[mi][nj], fAh[mi], fBl[nj], accf[mi][nj]);
                wmma::mma_sync(accf[mi][nj], fAl[mi], fBh[nj], accf[mi][nj]);
            }
        }
    }

    float* pb = g_P + (size_t)bh * ST_;
    #pragma unroll
    for (int mi = 0; mi < 4; ++mi) {
        #pragma unroll
        for (int nj = 0; nj < 2; ++nj) {
            #pragma unroll
            for (int e = 0; e < accf[mi][nj].num_elements; ++e)
                accf[mi][nj].x[e] *= 0.125f;
            wmma::store_matrix_sync(
                pb + (size_t)(blockM + warpM + mi * 16) * S_ + blockN + warpN + nj * 16,
                accf[mi][nj], S_, wmma::mem_row_major);
        }
    }
}

// ---------------------------------------------------------------------------
// Softmax over HEADS at each (b,s,t). FMA-pipe exp2 polynomial (no MUFU exp).
// Reads fp32 g_P, writes bf16 hi/lo g_Ph/g_Pl.
// ---------------------------------------------------------------------------
__device__ __forceinline__ float exp_poly(float x)
{
    float t = x * 1.4426950408889634f;
    t = fmaxf(t, -80.0f);
    float fi = floorf(t);
    float f = t - fi;
    float p = 0.0001540353f;
    p = p * f + 0.0013333558f;
    p = p * f + 0.0096181291f;
    p = p * f + 0.0555041087f;
    p = p * f + 0.2402265069f;
    p = p * f + 0.6931471806f;
    p = p * f + 1.0f;
    int ei = (int)fi + 127;
    float sc = __uint_as_float(((unsigned int)ei) << 23);
    return p * sc;
}

__global__ void __launch_bounds__(256)
softmax_heads()
{
    size_t id = (size_t)blockIdx.x * 256 + threadIdx.x;   // B*S*S points
    int t = (int)(id & 2047);
    int s = (int)((id >> 11) & 2047);
    int b = (int)(id >> 22);

    size_t base = (size_t)b * H_ * ST_ + (size_t)s * S_ + t;

    float v[H_];
    float mx = -1e30f;
    #pragma unroll
    for (int h = 0; h < H_; ++h) {
        v[h] = g_P[base + (size_t)h * ST_];
        mx = fmaxf(mx, v[h]);
    }
    float sum = 0.0f;
    #pragma unroll
    for (int h = 0; h < H_; ++h) {
        v[h] = exp_poly(v[h] - mx);
        sum += v[h];
    }
    float inv = __fdividef(1.0f, sum);
    #pragma unroll
    for (int h = 0; h < H_; ++h) {
        float p = v[h] * inv;
        __nv_bfloat16 ph = __float2bfloat16_rn(p);
        __nv_bfloat16 pl = __float2bfloat16_rn(p - __bfloat162float(ph));
        g_Ph[base + (size_t)h * ST_] = ph;
        g_Pl[base + (size_t)h * ST_] = pl;
    }
}

// ---------------------------------------------------------------------------
// AV: ctx[s][b][h*64+d] = sum_t P[bh][s][t] * V[bh][t][d], hi/lo split.
// BM=128, N=64, BK=64, 32 k-iters, 2-stage reg-prefetch pipeline.
// Loaders: P tile 128x64 -> 4 float4/thread/buffer; V tile 64x64 -> 2.
// ---------------------------------------------------------------------------
#define AV_PT_E   (128 * AKP)          // P tile elems per h/l
#define AV_VT_E   (64 * AKP)           // V tile elems per h/l
#define AV_STAGE  (2 * AV_PT_E + 2 * AV_VT_E)
#define AV_SMEM   (2 * AV_STAGE * 2)

__global__ void __launch_bounds__(256)
av_wmma()
{
    extern __shared__ __align__(16) unsigned char smraw[];
    __nv_bfloat16* smb = reinterpret_cast<__nv_bfloat16*>(smraw);

    const int tid    = threadIdx.x;
    const int warpid = tid >> 5;
    const int warpM  = (warpid >> 1) << 5;     // 0,32,64,96
    const int warpN  = (warpid & 1) << 5;      // 0,32
    const int blockM = blockIdx.x << 7;        // s tile
    const int bh     = blockIdx.y;
    const int bE     = bh >> 4;
    const int hE     = bh & 15;

    const __nv_bfloat16* gPh = g_Ph + (size_t)bh * ST_;
    const __nv_bfloat16* gPl = g_Pl + (size_t)bh * ST_;
    const __nv_bfloat16* gVh = g_Vh + (size_t)bh * (S_ * D_);
    const __nv_bfloat16* gVl = g_Vl + (size_t)bh * (S_ * D_);

    const int prow  = tid >> 1;                // 0..127
    const int phalf = tid & 1;
    const int vrow  = tid >> 2;                // 0..63
    const int vcol  = tid & 3;                 // 0..3 -> chunks 2v, 2v+1

    wmma::fragment<wmma::accumulator, 16, 16, 16, float> accf[2][2];
    #pragma unroll
    for (int mi = 0; mi < 2; ++mi)
        #pragma unroll
        for (int nj = 0; nj < 2; ++nj)
            wmma::fill_fragment(accf[mi][nj], 0.0f);

    float4 pre[12];        // [0..7]: P (c*2 + hl), [8..11]: V (chunk*2 + hl)
    #pragma unroll
    for (int c = 0; c < 4; ++c) {
        int scol = phalf * 4 + c;              // 0..7
        pre[c * 2 + 0] = *reinterpret_cast<const float4*>(
            gPh + (size_t)(blockM + prow) * S_ + scol * 8);
        pre[c * 2 + 1] = *reinterpret_cast<const float4*>(
            gPl + (size_t)(blockM + prow) * S_ + scol * 8);
    }
    #pragma unroll
    for (int c = 0; c < 2; ++c) {
        int scol = vcol * 2 + c;               // 0..7
        pre[8 + c * 2 + 0] = *reinterpret_cast<const float4*>(
            gVh + (size_t)vrow * 64 + scol * 8);
        pre[8 + c * 2 + 1] = *reinterpret_cast<const float4*>(
            gVl + (size_t)vrow * 64 + scol * 8);
    }

    {
        __nv_bfloat16* st = smb;
        #pragma unroll
        for (int c = 0; c < 4; ++c) {
            int scol = phalf * 4 + c;
            *reinterpret_cast<float4*>(st + prow * AKP + scol * 8) = pre[c * 2 + 0];
            *reinterpret_cast<float4*>(st + AV_PT_E + prow * AKP + scol * 8) = pre[c * 2 + 1];
        }
        #pragma unroll
        for (int c = 0; c < 2; ++c) {
            int scol = vcol * 2 + c;
            *reinterpret_cast<float4*>(st + 2 * AV_PT_E + vrow * AKP + scol * 8) = pre[8 + c * 2 + 0];
            *reinterpret_cast<float4*>(st + 2 * AV_PT_E + AV_VT_E + vrow * AKP + scol * 8) = pre[8 + c * 2 + 1];
        }
    }

    for (int step = 0; step < 32; ++step) {
        if (step < 31) {
            size_t k0 = (size_t)(step + 1) * 64;
            #pragma unroll
            for (int c = 0; c < 4; ++c) {
                int scol = phalf * 4 + c;
                pre[c * 2 + 0] = *reinterpret_cast<const float4*>(
                    gPh + (size_t)(blockM + prow) * S_ + k0 + scol * 8);
                pre[c * 2 + 1] = *reinterpret_cast<const float4*>(
                    gPl + (size_t)(blockM + prow) * S_ + k0 + scol * 8);
            }
            #pragma unroll
            for (int c = 0; c < 2; ++c) {
                int scol = vcol * 2 + c;
                pre[8 + c * 2 + 0] = *reinterpret_cast<const float4*>(
                    gVh + (size_t)(k0 + vrow) * 64 + scol * 8);
                pre[8 + c * 2 + 1] = *reinterpret_cast<const float4*>(
                    gVl + (size_t)(k0 + vrow) * 64 + scol * 8);
            }
        }
        __syncthreads();

        const __nv_bfloat16* st = smb + (step & 1) * AV_STAGE;
        const __nv_bfloat16* sPh = st;
        const __nv_bfloat16* sPl = st + AV_PT_E;
        const __nv_bfloat16* sVh = st + 2 * AV_PT_E;
        const __nv_bfloat16* sVl = st + 2 * AV_PT_E + AV_VT_E;

        #pragma unroll
        for (int kk = 0; kk < 4; ++kk) {
            wmma::fragment<wmma::matrix_a, 16, 16, 16, __nv_bfloat16, wmma::row_major> fAh[2];
            wmma::fragment<wmma::matrix_a, 16, 16, 16, __nv_bfloat16, wmma::row_major> fAl[2];
            wmma::fragment<wmma::matrix_b, 16, 16, 16, __nv_bfloat16, wmma::row_major> fBh[2];
            wmma::fragment<wmma::matrix_b, 16, 16, 16, __nv_bfloat16, wmma::row_major> fBl[2];
            #pragma unroll
            for (int mi = 0; mi < 2; ++mi) {
                wmma::load_matrix_sync(fAh[mi], sPh + (warpM + mi * 16) * AKP + kk * 16, AKP);
                wmma::load_matrix_sync(fAl[mi], sPl + (warpM + mi * 16) * AKP + kk * 16, AKP);
            }
            #pragma unroll
            for (int nj = 0; nj < 2; ++nj) {
                wmma::load_matrix_sync(fBh[nj], sVh + (kk * 16) * AKP + warpN + nj * 16, AKP);
                wmma::load_matrix_sync(fBl[nj], sVl + (kk * 16) * AKP + warpN + nj * 16, AKP);
            }
            #pragma unroll
            for (int mi = 0; mi < 2; ++mi) {
                #pragma unroll
                for (int nj = 0; nj < 2; ++nj) {
                    wmma::mma_sync(accf[mi][nj], fAh[mi], fBh[nj], accf[mi][nj]);
                    wmma::mma_sync(accf[mi][nj], fAh[mi], fBl[nj], accf[mi][nj]);
                    wmma::mma_sync(accf[mi][nj], fAl[mi], fBh[nj], accf[mi][nj]);
                }
            }
        }
        if (step < 31) {
            __nv_bfloat16* nst = smb + ((step + 1) & 1) * AV_STAGE;
            #pragma unroll
            for (int c = 0; c < 4; ++c) {
                int scol = phalf * 4 + c;
                *reinterpret_cast<float4*>(nst + prow * AKP + scol * 8) = pre[c * 2 + 0];
                *reinterpret_cast<float4*>(nst + AV_PT_E + prow * AKP + scol * 8) = pre[c * 2 + 1];
            }
            #pragma unroll
            for (int c = 0; c < 2; ++c) {
                int scol = vcol * 2 + c;
                *reinterpret_cast<float4*>(nst + 2 * AV_PT_E + vrow * AKP + scol * 8) = pre[8 + c * 2 + 0];
                *reinterpret_cast<float4*>(nst + 2 * AV_PT_E + AV_VT_E + vrow * AKP + scol * 8) = pre[8 + c * 2 + 1];
            }
        }
    }

    // ctx[s][b][h*64+d]: row stride B_*E_ = 2048 floats
    #pragma unroll
    for (int mi = 0; mi < 2; ++mi) {
        #pragma unroll
        for (int nj = 0; nj < 2; ++nj) {
            float* pd = g_ctx + (size_t)(blockM + warpM + mi * 16) * (B_ * E_)
                      + (size_t)bE * E_ + hE * 64 + warpN + nj * 16;
            wmma::store_matrix_sync(pd, accf[mi][nj], B_ * E_, wmma::mem_row_major);
        }
    }
}

// ---------------------------------------------------------------------------
// Launch. Inputs (metadata order): x, Wq, bq, Wk, bk, Wv, bv, Wo, bo
// ---------------------------------------------------------------------------
extern "C" void kernel_launch(void* const* d_in, const int* in_sizes, int n_in,
                              void* d_out, int out_size)
{
    const float* x  = (const float*)d_in[0];
    const float* Wq = (const float*)d_in[1];
    const float* bq = (const float*)d_in[2];
    const float* Wk = (const float*)d_in[3];
    const float* bk = (const float*)d_in[4];
    const float* Wv = (const float*)d_in[5];
    const float* bv = (const float*)d_in[6];
    const float* Wo = (const float*)d_in[7];
    const float* bo = (const float*)d_in[8];
    float* out = (float*)d_out;

    cudaFuncSetAttribute(wmma_gemm,
                         cudaFuncAttributeMaxDynamicSharedMemorySize, GEMM_SMEM);
    cudaFuncSetAttribute(scores_wmma,
                         cudaFuncAttributeMaxDynamicSharedMemorySize, SC_SMEM);
    cudaFuncSetAttribute(av_wmma,
                         cudaFuncAttributeMaxDynamicSharedMemorySize, AV_SMEM);

    __nv_bfloat16* xh;
    __nv_bfloat16* xl;
    __nv_bfloat16* Wh;
    __nv_bfloat16* Wl;
    __nv_bfloat16* ch;
    __nv_bfloat16* cl;
    float* ctxp;
    cudaGetSymbolAddress((void**)&xh, g_xh);
    cudaGetSymbolAddress((void**)&xl, g_xl);
    cudaGetSymbolAddress((void**)&Wh, g_Wh);
    cudaGetSymbolAddress((void**)&Wl, g_Wl);
    cudaGetSymbolAddress((void**)&ch, g_ch);
    cudaGetSymbolAddress((void**)&cl, g_cl);
    cudaGetSymbolAddress((void**)&ctxp, g_ctx);

    const size_t WSZ = (size_t)E_ * E_;
    dim3 blk(256);

    conv_split<<<(M_ * E_ / 4 + 255) / 256, blk>>>(x,  xh, xl, M_ * E_ / 4);
    conv_split<<<(WSZ / 4 + 255) / 256, blk>>>(Wq, Wh + 0 * WSZ, Wl + 0 * WSZ, WSZ / 4);
    conv_split<<<(WSZ / 4 + 255) / 256, blk>>>(Wk, Wh + 1 * WSZ, Wl + 1 * WSZ, WSZ / 4);
    conv_split<<<(WSZ / 4 + 255) / 256, blk>>>(Wv, Wh + 2 * WSZ, Wl + 2 * WSZ, WSZ / 4);
    conv_split<<<(WSZ / 4 + 255) / 256, blk>>>(Wo, Wh + 3 * WSZ, Wl + 3 * WSZ, WSZ / 4);

    dim3 gGemm(E_ / 128, M_ / 128);
    wmma_gemm<<<gGemm, blk, GEMM_SMEM>>>(xh, xl, Wh + 0 * WSZ, Wl + 0 * WSZ,
                                         bq, nullptr, 0);
    wmma_gemm<<<gGemm, blk, GEMM_SMEM>>>(xh, xl, Wh + 1 * WSZ, Wl + 1 * WSZ,
                                         bk, nullptr, 1);
    wmma_gemm<<<gGemm, blk, GEMM_SMEM>>>(xh, xl, Wh + 2 * WSZ, Wl + 2 * WSZ,
                                         bv, nullptr, 2);

    scores_wmma<<<dim3(S_ / 128, S_ / 128, BHn), blk, SC_SMEM>>>();
    softmax_heads<<<(unsigned)((size_t)B_ * S_ * S_ / 256), blk>>>();
    av_wmma<<<dim3(S_ / 128, BHn), blk, AV_SMEM>>>();

    conv_split<<<(M_ * E_ / 4 + 255) / 256, blk>>>(ctxp, ch, cl, M_ * E_ / 4);
    wmma_gemm<<<gGemm, blk, GEMM_SMEM>>>(ch, cl, Wh + 3 * WSZ, Wl + 3 * WSZ,
                                         bo, out, 3);
}